// round 2
// baseline (speedup 1.0000x reference)
#include <cuda_runtime.h>
#include <cstddef>
#include <cstdint>

// ---------------- problem constants ----------------
#define TT   336
#define NN   3233
#define EE   20000
#define FEAT 14
#define DD   64
#define HH   128
#define G4   512           // 4*H gate width
#define KTOT 192           // D + H contraction length (x part + h part)
#define MNODES 22
#define NBLK 147           // ceil(3233/22)

// ---------------- device scratch (static; no allocations) ----------------
__device__ float g_deg[NN];
__device__ float g_dinv[NN];
__device__ int   g_cnt[NN];
__device__ int   g_fill[NN];
__device__ int   g_rowptr[NN + 1];
__device__ int   g_srcs[EE];
__device__ float g_norms[EE];

__device__ float g_hw1[(size_t)TT * NN * DD];   // x @ W1
__device__ float g_h1 [(size_t)TT * NN * DD];   // relu(agg1)
__device__ float g_hw2[(size_t)TT * NN * DD];   // h1 @ W2
__device__ float g_emb[(size_t)TT * NN * DD];   // agg2 + county_bias

__device__ float4 g_WT4[KTOT / 4 * G4];         // [kk][j][4] combined W_ih|W_hh, k-transposed
__device__ float  g_bsum[G4];                   // b_ih + b_hh
__device__ float  g_hfinal[NN * HH];

// ---------------- fast, accurate activations ----------------
__device__ __forceinline__ float sigf(float x) {
    return __fdividef(1.0f, 1.0f + __expf(-x));      // MUFU.EX2 + MUFU.RCP, err ~1e-6
}
__device__ __forceinline__ float tanhf_fast(float x) {
    return 2.0f * sigf(2.0f * x) - 1.0f;
}

// ---------------- graph prep ----------------
__global__ void k_init() {
    int n = blockIdx.x * blockDim.x + threadIdx.x;
    if (n < NN) { g_deg[n] = 1.0f; g_cnt[n] = 0; g_fill[n] = 0; }  // self-loop weight 1
}

__global__ void k_deg(const int* __restrict__ ei, const float* __restrict__ ew) {
    int e = blockIdx.x * blockDim.x + threadIdx.x;
    if (e < EE) {
        int dn = ei[EE + e];
        atomicAdd(&g_deg[dn], ew[e]);
        atomicAdd(&g_cnt[dn], 1);
    }
}

__global__ void k_dinv() {
    int n = blockIdx.x * blockDim.x + threadIdx.x;
    if (n < NN) g_dinv[n] = rsqrtf(g_deg[n]);        // deg >= 1 always
}

// exclusive scan of g_cnt -> g_rowptr (single block, 1024 threads, 4 items/thread)
__global__ void k_scan() {
    __shared__ int warpsum[32];
    int tid = threadIdx.x;
    int base = tid * 4;
    int v[4]; int s = 0;
    #pragma unroll
    for (int i = 0; i < 4; i++) {
        int c = (base + i < NN) ? g_cnt[base + i] : 0;
        v[i] = s; s += c;
    }
    int lane = tid & 31, wid = tid >> 5;
    int inc = s;
    #pragma unroll
    for (int o = 1; o < 32; o <<= 1) {
        int t2 = __shfl_up_sync(0xffffffffu, inc, o);
        if (lane >= o) inc += t2;
    }
    if (lane == 31) warpsum[wid] = inc;
    __syncthreads();
    if (wid == 0) {
        int ws = warpsum[lane];
        #pragma unroll
        for (int o = 1; o < 32; o <<= 1) {
            int t2 = __shfl_up_sync(0xffffffffu, ws, o);
            if (lane >= o) ws += t2;
        }
        warpsum[lane] = ws;
    }
    __syncthreads();
    int excl = inc - s + (wid ? warpsum[wid - 1] : 0);
    #pragma unroll
    for (int i = 0; i < 4; i++)
        if (base + i < NN) g_rowptr[base + i] = excl + v[i];
    if (tid == 1023) g_rowptr[NN] = excl + s;
}

__global__ void k_fill(const int* __restrict__ ei, const float* __restrict__ ew) {
    int e = blockIdx.x * blockDim.x + threadIdx.x;
    if (e < EE) {
        int sn = ei[e], dn = ei[EE + e];
        int pos = g_rowptr[dn] + atomicAdd(&g_fill[dn], 1);
        g_srcs[pos]  = sn;
        g_norms[pos] = g_dinv[sn] * ew[e] * g_dinv[dn];
    }
}

// ---------------- weight prep: fold W_ih|W_hh -> k-transposed float4 layout ----------------
__global__ void k_prepw(const float* __restrict__ Wih, const float* __restrict__ Whh,
                        const float* __restrict__ bih, const float* __restrict__ bhh) {
    int idx = blockIdx.x * blockDim.x + threadIdx.x;      // over G4*KTOT
    if (idx < G4 * KTOT) {
        int j = idx / KTOT, k = idx % KTOT;
        float v = (k < DD) ? Wih[j * DD + k] : Whh[j * HH + (k - DD)];
        int kk = k >> 2, l = k & 3;
        ((float*)g_WT4)[(size_t)(kk * G4 + j) * 4 + l] = v;
    }
    if (idx < G4) g_bsum[idx] = bih[idx] + bhh[idx];
}

// ---------------- GCN1 transform: hw1 = x @ W1  (14 -> 64) ----------------
__global__ __launch_bounds__(256) void k_gcn1(const float* __restrict__ x,
                                              const float* __restrict__ W1) {
    int d = threadIdx.x & 63;
    float wcol[FEAT];
    #pragma unroll
    for (int f = 0; f < FEAT; f++) wcol[f] = W1[f * DD + d];
    __shared__ float xs[4][FEAT];
    size_t totalRows = (size_t)TT * NN;                   // divisible by 4
    for (size_t r0 = (size_t)blockIdx.x * 4; r0 < totalRows; r0 += (size_t)gridDim.x * 4) {
        __syncthreads();
        if (threadIdx.x < 4 * FEAT)
            ((float*)xs)[threadIdx.x] = x[r0 * FEAT + threadIdx.x];
        __syncthreads();
        int rr = threadIdx.x >> 6;
        float acc = 0.0f;
        #pragma unroll
        for (int f = 0; f < FEAT; f++) acc = fmaf(xs[rr][f], wcol[f], acc);
        g_hw1[r0 * DD + threadIdx.x] = acc;
    }
}

// ---------------- GCN2 transform: hw2 = h1 @ W2 (64 -> 64), W column in registers ----------------
__global__ __launch_bounds__(256) void k_gcn2(const float* __restrict__ W2) {
    int d = threadIdx.x & 63;
    float wcol[DD];
    #pragma unroll
    for (int f = 0; f < DD; f++) wcol[f] = W2[f * DD + d];
    __shared__ __align__(16) float rows[4][DD];
    size_t totalRows = (size_t)TT * NN;
    for (size_t r0 = (size_t)blockIdx.x * 4; r0 < totalRows; r0 += (size_t)gridDim.x * 4) {
        __syncthreads();
        ((float*)rows)[threadIdx.x] = g_h1[r0 * DD + threadIdx.x];
        __syncthreads();
        int rr = threadIdx.x >> 6;
        float acc = 0.0f;
        #pragma unroll
        for (int f = 0; f < DD; f += 4) {
            float4 a = *(const float4*)&rows[rr][f];
            acc = fmaf(a.x, wcol[f],     acc);
            acc = fmaf(a.y, wcol[f + 1], acc);
            acc = fmaf(a.z, wcol[f + 2], acc);
            acc = fmaf(a.w, wcol[f + 3], acc);
        }
        g_hw2[r0 * DD + threadIdx.x] = acc;
    }
}

// ---------------- GCN aggregation (gather form over CSR-by-dst, + self loop) ----------------
// Each block handles one node n and TWO timesteps (t0, t0+1): the edge structure
// is t-invariant, so index loads amortize across both.
// layer 1: out = relu(agg(hw1) + b1) -> g_h1
// layer 2: out = agg(hw2) + b2 + county_bias -> g_emb
__global__ void k_agg(int layer, const float* __restrict__ b, const float* __restrict__ cb) {
    int n = blockIdx.x, t0 = blockIdx.y * 2, d = threadIdx.x;
    const float* hw = (layer == 1) ? g_hw1 : g_hw2;
    const float* hwt0 = hw + (size_t)t0 * NN * DD;
    const float* hwt1 = hwt0 + (size_t)NN * DD;
    float di = g_dinv[n];
    float sw = di * di;
    float acc0 = sw * __ldg(&hwt0[(size_t)n * DD + d]);
    float acc1 = sw * __ldg(&hwt1[(size_t)n * DD + d]);
    int s = g_rowptr[n], e = g_rowptr[n + 1];
    for (int i = s; i < e; i++) {
        int    sn = g_srcs[i];
        float  w  = g_norms[i];
        size_t o  = (size_t)sn * DD + d;
        acc0 = fmaf(w, __ldg(&hwt0[o]), acc0);
        acc1 = fmaf(w, __ldg(&hwt1[o]), acc1);
    }
    float bv = b[d];
    acc0 += bv; acc1 += bv;
    float* o;
    if (layer == 1) {
        acc0 = fmaxf(acc0, 0.0f); acc1 = fmaxf(acc1, 0.0f); o = g_h1;
    } else {
        float cbv = cb[(size_t)n * DD + d];
        acc0 += cbv; acc1 += cbv; o = g_emb;
    }
    o[((size_t)t0 * NN + n) * DD + d] = acc0;
    o[((size_t)(t0 + 1) * NN + n) * DD + d] = acc1;
}

// ---------------- persistent LSTM: per-block node tile, state in shared, W streamed from L2 ----------------
__global__ __launch_bounds__(256) void k_lstm() {
    __shared__ __align__(16) float a_s[MNODES][KTOT];   // [x(64) | h(128)] per node
    __shared__ float c_s[MNODES][HH];
    __shared__ float p_s[MNODES][HH];                   // sig(i)*tanh(g)

    int tid = threadIdx.x;
    int nb  = blockIdx.x * MNODES;
    int mcnt = min(MNODES, NN - nb);

    // zero state (h region of a_s and c_s); x region overwritten each step (row 21 of a
    // partial last block stays 0 -> bounded garbage, never written out)
    for (int i = tid; i < MNODES * KTOT; i += 256) ((float*)a_s)[i] = 0.0f;
    for (int i = tid; i < MNODES * HH;   i += 256) ((float*)c_s)[i] = 0.0f;

    float bias0 = g_bsum[tid];
    float bias1 = g_bsum[tid + 256];
    __syncthreads();

    for (int t = 0; t < TT; t++) {
        // load x_t tile (coalesced rows of embeds)
        const float* xin = g_emb + ((size_t)t * NN + nb) * DD;
        for (int i = tid; i < mcnt * DD; i += 256) {
            int m = i >> 6, f = i & 63;
            a_s[m][f] = xin[i];
        }
        __syncthreads();

        // G = bias + [x|h] @ Wcomb^T ; thread owns gate columns tid and tid+256
        float acc0[MNODES], acc1[MNODES];
        #pragma unroll
        for (int m = 0; m < MNODES; m++) { acc0[m] = bias0; acc1[m] = bias1; }

        float4 w0 = g_WT4[tid];
        float4 w1 = g_WT4[tid + 256];
        #pragma unroll 1
        for (int kk = 0; kk < KTOT / 4; kk++) {
            int nk = (kk + 1 < KTOT / 4) ? kk + 1 : kk;   // prefetch next weights (L2-resident)
            float4 nw0 = g_WT4[nk * G4 + tid];
            float4 nw1 = g_WT4[nk * G4 + tid + 256];
            #pragma unroll
            for (int m = 0; m < MNODES; m++) {
                float4 a = *(const float4*)&a_s[m][kk * 4];  // warp-uniform broadcast LDS.128
                acc0[m] = fmaf(a.x, w0.x, acc0[m]);
                acc0[m] = fmaf(a.y, w0.y, acc0[m]);
                acc0[m] = fmaf(a.z, w0.z, acc0[m]);
                acc0[m] = fmaf(a.w, w0.w, acc0[m]);
                acc1[m] = fmaf(a.x, w1.x, acc1[m]);
                acc1[m] = fmaf(a.y, w1.y, acc1[m]);
                acc1[m] = fmaf(a.z, w1.z, acc1[m]);
                acc1[m] = fmaf(a.w, w1.w, acc1[m]);
            }
            w0 = nw0; w1 = nw1;
        }

        // gates: tid<128 holds (i_u, g_u); tid>=128 holds (f_u, o_u), u = tid&127
        if (tid < 128) {
            int u = tid;
            #pragma unroll
            for (int m = 0; m < MNODES; m++)
                p_s[m][u] = sigf(acc0[m]) * tanhf_fast(acc1[m]);
        }
        __syncthreads();   // also fences all a_s reads of the GEMM phase
        if (tid >= 128) {
            int u = tid - 128;
            #pragma unroll
            for (int m = 0; m < MNODES; m++) {
                float fs = sigf(acc0[m]);
                float os = sigf(acc1[m]);
                float c  = fmaf(fs, c_s[m][u], p_s[m][u]);
                c_s[m][u] = c;
                a_s[m][DD + u] = os * tanhf_fast(c);
            }
        }
        __syncthreads();
    }

    // write final hidden state
    for (int i = tid; i < mcnt * HH; i += 256) {
        int m = i >> 7, u = i & 127;
        g_hfinal[(size_t)(nb + m) * HH + u] = a_s[m][DD + u];
    }
}

// ---------------- head MLP: out = relu(hf @ Wm1 + bm1) @ Wm2 + bm2 ----------------
__global__ void k_head(const float* __restrict__ Wm1, const float* __restrict__ bm1,
                       const float* __restrict__ Wm2, const float* __restrict__ bm2,
                       float* __restrict__ out) {
    __shared__ float hrow[HH];
    __shared__ float zred[2];
    int n = blockIdx.x, d = threadIdx.x;
    for (int i = d; i < HH; i += 64) hrow[i] = g_hfinal[(size_t)n * HH + i];
    __syncthreads();
    float acc = bm1[d];
    #pragma unroll 8
    for (int k = 0; k < HH; k++) acc = fmaf(hrow[k], Wm1[k * 64 + d], acc);
    acc = fmaxf(acc, 0.0f) * Wm2[d];
    #pragma unroll
    for (int o = 16; o; o >>= 1) acc += __shfl_down_sync(0xffffffffu, acc, o);
    if ((d & 31) == 0) zred[d >> 5] = acc;
    __syncthreads();
    if (d == 0) out[n] = zred[0] + zred[1] + bm2[0];
}

// ---------------- launch ----------------
extern "C" void kernel_launch(void* const* d_in, const int* in_sizes, int n_in,
                              void* d_out, int out_size) {
    (void)in_sizes; (void)n_in; (void)out_size;
    const float* x    = (const float*)d_in[0];
    const int*   ei   = (const int*)  d_in[1];
    const float* ew   = (const float*)d_in[2];
    const float* W1   = (const float*)d_in[3];
    const float* b1   = (const float*)d_in[4];
    const float* W2   = (const float*)d_in[5];
    const float* b2   = (const float*)d_in[6];
    const float* cb   = (const float*)d_in[7];
    const float* Wih  = (const float*)d_in[8];
    const float* Whh  = (const float*)d_in[9];
    const float* bih  = (const float*)d_in[10];
    const float* bhh  = (const float*)d_in[11];
    const float* Wm1  = (const float*)d_in[12];
    const float* bm1  = (const float*)d_in[13];
    const float* Wm2  = (const float*)d_in[14];
    const float* bm2  = (const float*)d_in[15];
    float* out = (float*)d_out;

    k_init<<<(NN + 255) / 256, 256>>>();
    k_deg <<<(EE + 255) / 256, 256>>>(ei, ew);
    k_dinv<<<(NN + 255) / 256, 256>>>();
    k_scan<<<1, 1024>>>();
    k_fill<<<(EE + 255) / 256, 256>>>(ei, ew);
    k_prepw<<<(G4 * KTOT + 255) / 256, 256>>>(Wih, Whh, bih, bhh);

    k_gcn1<<<4096, 256>>>(x, W1);
    dim3 aggGrid(NN, TT / 2);          // TT=336 even: 2 timesteps per block
    k_agg<<<aggGrid, 64>>>(1, b1, nullptr);
    k_gcn2<<<4096, 256>>>(W2);
    k_agg<<<aggGrid, 64>>>(2, b2, cb);

    k_lstm<<<NBLK, 256>>>();
    k_head<<<NN, 64>>>(Wm1, bm1, Wm2, bm2, out);
}